// round 3
// baseline (speedup 1.0000x reference)
#include <cuda_runtime.h>
#include <stdint.h>

#define BB 8
#define LQ 512
#define LC 2048
#define DD 768
#define CT 16
#define SC_PITCH 20
#define NTHREADS 256

typedef unsigned long long ull;

// Packed 2x fp32 FMA — ptxas never emits FFMA2 from C++; PTX only.
__device__ __forceinline__ ull fma2(ull a, ull b, ull c) {
    ull d;
    asm("fma.rn.f32x2 %0, %1, %2, %3;" : "=l"(d) : "l"(a), "l"(b), "l"(c));
    return d;
}
__device__ __forceinline__ ull pack2(float lo, float hi) {
    ull r;
    asm("mov.b64 %0, {%1, %2};" : "=l"(r) : "f"(lo), "f"(hi));
    return r;
}
__device__ __forceinline__ float2 unpack2(ull v) {
    float2 r;
    asm("mov.b64 {%0, %1}, %2;" : "=f"(r.x), "=f"(r.y) : "l"(v));
    return r;
}

__global__ __launch_bounds__(NTHREADS, 2)
void gated_attn_kernel(const float* __restrict__ ctx,
                       const float* __restrict__ qry,
                       float* __restrict__ out)
{
    extern __shared__ float smem[];
    float* ctx_s = smem;                          // CT*DD floats (48 KB)
    float* sc    = smem + CT * DD;                // LQ*SC_PITCH floats (40 KB)
    float* inv_s = smem + CT * DD + LQ * SC_PITCH; // 16 floats

    const int tid  = threadIdx.x;
    const int w    = tid >> 5;
    const int lane = tid & 31;
    const int b    = blockIdx.y;
    const int c0   = blockIdx.x * CT;

    const float* ctxB = ctx + ((size_t)b * LC + c0) * DD;
    const float* qB   = qry + (size_t)b * LQ * DD;
    float*       outB = out + ((size_t)b * LC + c0) * DD;

    // ---- Phase 0: stage context tile (rows are contiguous in gmem) ----
    {
        const float4* src4 = (const float4*)ctxB;
        float4*       dst4 = (float4*)ctx_s;
        #pragma unroll
        for (int i = tid; i < CT * DD / 4; i += NTHREADS) dst4[i] = src4[i];
    }
    __syncthreads();

    // ---- Phase 1: S[q,c] = Q[q,:] . C[c,:]  (warp per 4 q-rows, f32x2) ----
    for (int it = 0; it < 16; ++it) {
        const int q = (w << 6) + (it << 2);
        ull qv[4][12];
        #pragma unroll
        for (int r = 0; r < 4; r++) {
            const ull* qp = (const ull*)(qB + (size_t)(q + r) * DD);
            #pragma unroll
            for (int k = 0; k < 12; k++) qv[r][k] = qp[lane + (k << 5)];
        }
        #pragma unroll
        for (int c = 0; c < CT; c++) {
            const ull* cp = (const ull*)(ctx_s + c * DD);
            ull a0 = 0ull, a1 = 0ull, a2 = 0ull, a3 = 0ull;
            #pragma unroll
            for (int k = 0; k < 12; k++) {
                ull cv = cp[lane + (k << 5)];
                a0 = fma2(qv[0][k], cv, a0);
                a1 = fma2(qv[1][k], cv, a1);
                a2 = fma2(qv[2][k], cv, a2);
                a3 = fma2(qv[3][k], cv, a3);
            }
            float2 f0 = unpack2(a0), f1 = unpack2(a1), f2 = unpack2(a2), f3 = unpack2(a3);
            float s0 = f0.x + f0.y, s1 = f1.x + f1.y, s2 = f2.x + f2.y, s3 = f3.x + f3.y;
            #pragma unroll
            for (int off = 16; off; off >>= 1) {
                s0 += __shfl_xor_sync(0xffffffffu, s0, off);
                s1 += __shfl_xor_sync(0xffffffffu, s1, off);
                s2 += __shfl_xor_sync(0xffffffffu, s2, off);
                s3 += __shfl_xor_sync(0xffffffffu, s3, off);
            }
            if (lane == 0) {
                sc[(q + 0) * SC_PITCH + c] = s0;
                sc[(q + 1) * SC_PITCH + c] = s1;
                sc[(q + 2) * SC_PITCH + c] = s2;
                sc[(q + 3) * SC_PITCH + c] = s3;
            }
        }
    }
    __syncthreads();

    // ---- Phase 2: softmax over q for each c; keep exp in sc, 1/sum in inv_s ----
    for (int cc = w; cc < CT; cc += 8) {
        float m = -3.0e38f;
        for (int q = lane; q < LQ; q += 32) m = fmaxf(m, sc[q * SC_PITCH + cc]);
        #pragma unroll
        for (int off = 16; off; off >>= 1)
            m = fmaxf(m, __shfl_xor_sync(0xffffffffu, m, off));
        float s = 0.f;
        for (int q = lane; q < LQ; q += 32) {
            float e = __expf(sc[q * SC_PITCH + cc] - m);
            sc[q * SC_PITCH + cc] = e;
            s += e;
        }
        #pragma unroll
        for (int off = 16; off; off >>= 1)
            s += __shfl_xor_sync(0xffffffffu, s, off);
        if (lane == 0) inv_s[cc] = 1.0f / s;
    }
    __syncthreads();

    // ---- Phase 3: AWQ[c,d] = sum_q alpha[q,c] * Q[q,d]  (packed over c-pairs) ----
    ull acc[8][3];
    #pragma unroll
    for (int p = 0; p < 8; p++)
        #pragma unroll
        for (int j = 0; j < 3; j++) acc[p][j] = 0ull;

    for (int q = 0; q < LQ; q++) {
        const float* qr = qB + (size_t)q * DD;
        ull qq[3];
        #pragma unroll
        for (int j = 0; j < 3; j++) {
            float v = qr[tid + j * NTHREADS];
            qq[j] = pack2(v, v);
        }
        const ull* ar = (const ull*)(sc + q * SC_PITCH);   // 16 alphas = 8 packed pairs
        #pragma unroll
        for (int p = 0; p < 8; p++) {
            ull a2v = ar[p];
            acc[p][0] = fma2(a2v, qq[0], acc[p][0]);
            acc[p][1] = fma2(a2v, qq[1], acc[p][1]);
            acc[p][2] = fma2(a2v, qq[2], acc[p][2]);
        }
    }

    // ---- Phase 4: normalize, gate against context, store ----
    #pragma unroll
    for (int p = 0; p < 8; p++) {
        float i0 = inv_s[2 * p], i1 = inv_s[2 * p + 1];
        #pragma unroll
        for (int j = 0; j < 3; j++) {
            int d = tid + j * NTHREADS;
            float2 v = unpack2(acc[p][j]);
            outB[(size_t)(2 * p) * DD + d]     = ctx_s[(2 * p) * DD + d]     * (v.x * i0);
            outB[(size_t)(2 * p + 1) * DD + d] = ctx_s[(2 * p + 1) * DD + d] * (v.y * i1);
        }
    }
}

extern "C" void kernel_launch(void* const* d_in, const int* in_sizes, int n_in,
                              void* d_out, int out_size)
{
    const float* a0 = (const float*)d_in[0];
    const float* a1 = (const float*)d_in[1];
    const float* ctx;
    const float* qry;
    if (in_sizes[0] == BB * LC * DD) { ctx = a0; qry = a1; }
    else                             { ctx = a1; qry = a0; }

    const int smem_bytes = (CT * DD + LQ * SC_PITCH + 16) * (int)sizeof(float); // 90176
    cudaFuncSetAttribute(gated_attn_kernel,
                         cudaFuncAttributeMaxDynamicSharedMemorySize, smem_bytes);

    dim3 grid(LC / CT, BB);
    gated_attn_kernel<<<grid, NTHREADS, smem_bytes>>>(ctx, qry, (float*)d_out);
}

// round 4
// speedup vs baseline: 1.0011x; 1.0011x over previous
#include <cuda_runtime.h>
#include <stdint.h>

#define BB 8
#define LQ 512
#define LC 2048
#define DD 768
#define CT 16
#define SC_PITCH 20
#define NTHREADS 256

typedef unsigned long long ull;

// Packed 2x fp32 FMA — ptxas never emits FFMA2 from C++; PTX only.
__device__ __forceinline__ ull fma2(ull a, ull b, ull c) {
    ull d;
    asm("fma.rn.f32x2 %0, %1, %2, %3;" : "=l"(d) : "l"(a), "l"(b), "l"(c));
    return d;
}
__device__ __forceinline__ ull pack2(float lo, float hi) {
    ull r;
    asm("mov.b64 %0, {%1, %2};" : "=l"(r) : "f"(lo), "f"(hi));
    return r;
}
__device__ __forceinline__ float2 unpack2(ull v) {
    float2 r;
    asm("mov.b64 {%0, %1}, %2;" : "=f"(r.x), "=f"(r.y) : "l"(v));
    return r;
}

__global__ __launch_bounds__(NTHREADS, 2)
void gated_attn_kernel(const float* __restrict__ ctx,
                       const float* __restrict__ qry,
                       float* __restrict__ out)
{
    extern __shared__ float smem[];
    float* ctx_s = smem;                          // CT*DD floats (48 KB)
    float* sc    = smem + CT * DD;                // LQ*SC_PITCH floats (40 KB)
    float* inv_s = smem + CT * DD + LQ * SC_PITCH; // 16 floats

    const int tid  = threadIdx.x;
    const int w    = tid >> 5;
    const int lane = tid & 31;
    const int b    = blockIdx.y;
    const int c0   = blockIdx.x * CT;

    const float* ctxB = ctx + ((size_t)b * LC + c0) * DD;
    const float* qB   = qry + (size_t)b * LQ * DD;
    float*       outB = out + ((size_t)b * LC + c0) * DD;

    // ---- Phase 0: stage context tile (rows are contiguous in gmem) ----
    {
        const float4* src4 = (const float4*)ctxB;
        float4*       dst4 = (float4*)ctx_s;
        #pragma unroll
        for (int i = tid; i < CT * DD / 4; i += NTHREADS) dst4[i] = src4[i];
    }
    __syncthreads();

    // ---- Phase 1: S[q,c] = Q[q,:] . C[c,:]  (warp per 4 q-rows, f32x2) ----
    for (int it = 0; it < 16; ++it) {
        const int q = (w << 6) + (it << 2);
        ull qv[4][12];
        #pragma unroll
        for (int r = 0; r < 4; r++) {
            const ull* qp = (const ull*)(qB + (size_t)(q + r) * DD);
            #pragma unroll
            for (int k = 0; k < 12; k++) qv[r][k] = qp[lane + (k << 5)];
        }
        #pragma unroll
        for (int c = 0; c < CT; c++) {
            const ull* cp = (const ull*)(ctx_s + c * DD);
            ull a0 = 0ull, a1 = 0ull, a2 = 0ull, a3 = 0ull;
            #pragma unroll
            for (int k = 0; k < 12; k++) {
                ull cv = cp[lane + (k << 5)];
                a0 = fma2(qv[0][k], cv, a0);
                a1 = fma2(qv[1][k], cv, a1);
                a2 = fma2(qv[2][k], cv, a2);
                a3 = fma2(qv[3][k], cv, a3);
            }
            float2 f0 = unpack2(a0), f1 = unpack2(a1), f2 = unpack2(a2), f3 = unpack2(a3);
            float s0 = f0.x + f0.y, s1 = f1.x + f1.y, s2 = f2.x + f2.y, s3 = f3.x + f3.y;
            #pragma unroll
            for (int off = 16; off; off >>= 1) {
                s0 += __shfl_xor_sync(0xffffffffu, s0, off);
                s1 += __shfl_xor_sync(0xffffffffu, s1, off);
                s2 += __shfl_xor_sync(0xffffffffu, s2, off);
                s3 += __shfl_xor_sync(0xffffffffu, s3, off);
            }
            if (lane == 0) {
                sc[(q + 0) * SC_PITCH + c] = s0;
                sc[(q + 1) * SC_PITCH + c] = s1;
                sc[(q + 2) * SC_PITCH + c] = s2;
                sc[(q + 3) * SC_PITCH + c] = s3;
            }
        }
    }
    __syncthreads();

    // ---- Phase 2: softmax over q for each c; keep exp in sc, 1/sum in inv_s ----
    for (int cc = w; cc < CT; cc += 8) {
        float m = -3.0e38f;
        for (int q = lane; q < LQ; q += 32) m = fmaxf(m, sc[q * SC_PITCH + cc]);
        #pragma unroll
        for (int off = 16; off; off >>= 1)
            m = fmaxf(m, __shfl_xor_sync(0xffffffffu, m, off));
        float s = 0.f;
        for (int q = lane; q < LQ; q += 32) {
            float e = __expf(sc[q * SC_PITCH + cc] - m);
            sc[q * SC_PITCH + cc] = e;
            s += e;
        }
        #pragma unroll
        for (int off = 16; off; off >>= 1)
            s += __shfl_xor_sync(0xffffffffu, s, off);
        if (lane == 0) inv_s[cc] = 1.0f / s;
    }
    __syncthreads();

    // ---- Phase 3: AWQ[c,d] = sum_q alpha[q,c] * Q[q,d]  (packed over c-pairs) ----
    ull acc[8][3];
    #pragma unroll
    for (int p = 0; p < 8; p++)
        #pragma unroll
        for (int j = 0; j < 3; j++) acc[p][j] = 0ull;

    for (int q = 0; q < LQ; q++) {
        const float* qr = qB + (size_t)q * DD;
        ull qq[3];
        #pragma unroll
        for (int j = 0; j < 3; j++) {
            float v = qr[tid + j * NTHREADS];
            qq[j] = pack2(v, v);
        }
        const ull* ar = (const ull*)(sc + q * SC_PITCH);   // 16 alphas = 8 packed pairs
        #pragma unroll
        for (int p = 0; p < 8; p++) {
            ull a2v = ar[p];
            acc[p][0] = fma2(a2v, qq[0], acc[p][0]);
            acc[p][1] = fma2(a2v, qq[1], acc[p][1]);
            acc[p][2] = fma2(a2v, qq[2], acc[p][2]);
        }
    }

    // ---- Phase 4: normalize, gate against context, store ----
    #pragma unroll
    for (int p = 0; p < 8; p++) {
        float i0 = inv_s[2 * p], i1 = inv_s[2 * p + 1];
        #pragma unroll
        for (int j = 0; j < 3; j++) {
            int d = tid + j * NTHREADS;
            float2 v = unpack2(acc[p][j]);
            outB[(size_t)(2 * p) * DD + d]     = ctx_s[(2 * p) * DD + d]     * (v.x * i0);
            outB[(size_t)(2 * p + 1) * DD + d] = ctx_s[(2 * p + 1) * DD + d] * (v.y * i1);
        }
    }
}

extern "C" void kernel_launch(void* const* d_in, const int* in_sizes, int n_in,
                              void* d_out, int out_size)
{
    const float* a0 = (const float*)d_in[0];
    const float* a1 = (const float*)d_in[1];
    const float* ctx;
    const float* qry;
    if (in_sizes[0] == BB * LC * DD) { ctx = a0; qry = a1; }
    else                             { ctx = a1; qry = a0; }

    const int smem_bytes = (CT * DD + LQ * SC_PITCH + 16) * (int)sizeof(float); // 90176
    cudaFuncSetAttribute(gated_attn_kernel,
                         cudaFuncAttributeMaxDynamicSharedMemorySize, smem_bytes);

    dim3 grid(LC / CT, BB);
    gated_attn_kernel<<<grid, NTHREADS, smem_bytes>>>(ctx, qry, (float*)d_out);
}

// round 6
// speedup vs baseline: 2.1285x; 2.1262x over previous
#include <cuda_runtime.h>
#include <cuda_bf16.h>
#include <stdint.h>

typedef __nv_bfloat16 bf16;

#define BB 8
#define LQ 512
#define LC 2048
#define DD 768

// ---------------- scratch (device globals; allocation-free) ----------------
__device__ __align__(128) bf16  g_Chi[BB * LC * DD];
__device__ __align__(128) bf16  g_Clo[BB * LC * DD];
__device__ __align__(128) bf16  g_Qhi[BB * LQ * DD];
__device__ __align__(128) bf16  g_Qlo[BB * LQ * DD];
__device__ __align__(128) bf16  g_QThi[BB * DD * LQ];
__device__ __align__(128) bf16  g_QTlo[BB * DD * LQ];
__device__ __align__(128) float g_S[BB * LC * LQ];      // S_t[b][c][q]
__device__ __align__(128) bf16  g_Ahi[BB * LC * LQ];    // alpha_t hi
__device__ __align__(128) bf16  g_Alo[BB * LC * LQ];    // alpha_t lo

// ---------------- helpers ----------------
__device__ __forceinline__ uint32_t smem_u32(const void* p) {
    uint32_t a;
    asm("{ .reg .u64 t; cvta.to.shared.u64 t, %1; cvt.u32.u64 %0, t; }" : "=r"(a) : "l"(p));
    return a;
}
#define CP_ASYNC16(dst, src) \
    asm volatile("cp.async.cg.shared.global [%0], [%1], 16;" :: "r"(dst), "l"(src))
#define CP_COMMIT() asm volatile("cp.async.commit_group;" ::: "memory")
#define CP_WAIT2()  asm volatile("cp.async.wait_group 2;" ::: "memory")
#define CP_WAIT0()  asm volatile("cp.async.wait_group 0;" ::: "memory")

__device__ __forceinline__ void ldsm_x4(uint32_t* r, uint32_t a) {
    asm volatile("ldmatrix.sync.aligned.m8n8.x4.shared.b16 {%0,%1,%2,%3}, [%4];"
                 : "=r"(r[0]), "=r"(r[1]), "=r"(r[2]), "=r"(r[3]) : "r"(a));
}
__device__ __forceinline__ void mma16816(float* d, const uint32_t* a, const uint32_t* b) {
    asm volatile(
        "mma.sync.aligned.m16n8k16.row.col.f32.bf16.bf16.f32 "
        "{%0,%1,%2,%3}, {%4,%5,%6,%7}, {%8,%9}, {%0,%1,%2,%3};"
        : "+f"(d[0]), "+f"(d[1]), "+f"(d[2]), "+f"(d[3])
        : "r"(a[0]), "r"(a[1]), "r"(a[2]), "r"(a[3]), "r"(b[0]), "r"(b[1]));
}

__device__ __forceinline__ void split_bf16(float x, bf16& hi, bf16& lo) {
    hi = __float2bfloat16(x);
    lo = __float2bfloat16(x - __bfloat162float(hi));
}

// ---------------- kernel: elementwise split (used for C) ----------------
__global__ __launch_bounds__(256)
void split_kernel(const float* __restrict__ x, bf16* __restrict__ hi,
                  bf16* __restrict__ lo, int n4) {
    int i = blockIdx.x * 256 + threadIdx.x;
    if (i >= n4) return;
    float4 v = reinterpret_cast<const float4*>(x)[i];
    bf16 h0, l0, h1, l1, h2, l2, h3, l3;
    split_bf16(v.x, h0, l0); split_bf16(v.y, h1, l1);
    split_bf16(v.z, h2, l2); split_bf16(v.w, h3, l3);
    __nv_bfloat162* h2p = reinterpret_cast<__nv_bfloat162*>(hi) + 2 * i;
    __nv_bfloat162* l2p = reinterpret_cast<__nv_bfloat162*>(lo) + 2 * i;
    h2p[0] = __halves2bfloat162(h0, h1);
    h2p[1] = __halves2bfloat162(h2, h3);
    l2p[0] = __halves2bfloat162(l0, l1);
    l2p[1] = __halves2bfloat162(l2, l3);
}

// ---------------- kernel: Q split + transpose ----------------
__global__ __launch_bounds__(256)
void q_split_transpose(const float* __restrict__ q) {
    __shared__ float tile[32][33];
    int b  = blockIdx.z;
    int d0 = blockIdx.x * 32;
    int q0 = blockIdx.y * 32;
    int tx = threadIdx.x, ty = threadIdx.y;   // 32 x 8

    const float* src = q + ((size_t)b * LQ + q0) * DD + d0;
    #pragma unroll
    for (int i = 0; i < 4; i++) {
        int r = ty + i * 8;
        float v = src[(size_t)r * DD + tx];
        tile[r][tx] = v;
        bf16 h, l; split_bf16(v, h, l);
        size_t idx = ((size_t)b * LQ + q0 + r) * DD + d0 + tx;
        g_Qhi[idx] = h;
        g_Qlo[idx] = l;
    }
    __syncthreads();
    #pragma unroll
    for (int i = 0; i < 4; i++) {
        int r = ty + i * 8;                    // d offset
        float v = tile[tx][r];                 // = Q[q0+tx][d0+r]
        bf16 h, l; split_bf16(v, h, l);
        size_t idx = ((size_t)b * DD + d0 + r) * LQ + q0 + tx;
        g_QThi[idx] = h;
        g_QTlo[idx] = l;
    }
}

// ---------------- kernel: softmax over q (rows of S_t) + bf16 split ----------------
__global__ __launch_bounds__(256)
void softmax_split_kernel() {
    int wid = threadIdx.x >> 5, lane = threadIdx.x & 31;
    int row = blockIdx.x * 8 + wid;            // c index
    int b   = blockIdx.y;
    const float* p = g_S + ((size_t)b * LC + row) * LQ;
    float e[16];
    float m = -3.0e38f;
    #pragma unroll
    for (int i = 0; i < 16; i++) { e[i] = p[lane + i * 32]; m = fmaxf(m, e[i]); }
    #pragma unroll
    for (int off = 16; off; off >>= 1) m = fmaxf(m, __shfl_xor_sync(0xffffffffu, m, off));
    float s = 0.f;
    #pragma unroll
    for (int i = 0; i < 16; i++) { e[i] = expf(e[i] - m); s += e[i]; }
    #pragma unroll
    for (int off = 16; off; off >>= 1) s += __shfl_xor_sync(0xffffffffu, s, off);
    float inv = 1.0f / s;
    bf16* ah = g_Ahi + ((size_t)b * LC + row) * LQ;
    bf16* al = g_Alo + ((size_t)b * LC + row) * LQ;
    #pragma unroll
    for (int i = 0; i < 16; i++) {
        float a = e[i] * inv;
        bf16 h, l; split_bf16(a, h, l);
        ah[lane + i * 32] = h;
        al[lane + i * 32] = l;
    }
}

// ---------------- unified split-precision HMMA GEMM (+gating epilogue) --------
// D[m][n] = sum_k A[m][k]*B[n][k], computed as Ah*Bh + Ah*Bl + Al*Bh, fp32 acc.
// Block tile 128x128, 8 warps (2m x 4n), warp tile 64x32, KC=32, 3-stage cp.async.
#define PITCH    80        // 32 k (64B) + 16B pad -> conflict-free ldmatrix
#define STG_SIZE 40960     // 4 arrays * 128 rows * 80B
#define SM_TOTAL (3 * STG_SIZE)

__global__ __launch_bounds__(256, 1)
void gemm_split_hmma(const bf16* __restrict__ Ah, const bf16* __restrict__ Al,
                     int lda, long sAb,
                     const bf16* __restrict__ Bh, const bf16* __restrict__ Bl,
                     int ldb, long sBb,
                     int nchunks,
                     float* __restrict__ D, int ldd, long sDb,
                     const float* __restrict__ gate, int mode) {
    extern __shared__ char smem[];
    const uint32_t sbase = smem_u32(smem);
    const int tid = threadIdx.x, wid = tid >> 5, lane = tid & 31;
    const int b  = blockIdx.z;
    const int m0 = blockIdx.y * 128, n0 = blockIdx.x * 128;

    const bf16* Ahp = Ah + (size_t)b * sAb + (size_t)m0 * lda;
    const bf16* Alp = Al + (size_t)b * sAb + (size_t)m0 * lda;
    const bf16* Bhp = Bh + (size_t)b * sBb + (size_t)n0 * ldb;
    const bf16* Blp = Bl + (size_t)b * sBb + (size_t)n0 * ldb;

    // cp.async issue for one 32-k chunk into stage (chunk%3).
    auto issue = [&](int chunk) {
        const uint32_t st = sbase + (uint32_t)(chunk % 3) * STG_SIZE;
        const int k0 = chunk * 32;
        #pragma unroll
        for (int i = 0; i < 8; i++) {                    // i>>1: 0=Ah 1=Al 2=Bh 3=Bl
            const int u = i * 256 + tid;
            const int r = (u >> 2) & 127;
            const int c = u & 3;
            const bf16* base = (i < 2) ? Ahp : (i < 4) ? Alp : (i < 6) ? Bhp : Blp;
            const int ld = (i < 4) ? lda : ldb;
            const bf16* src = base + (size_t)r * ld + k0 + c * 8;
            const uint32_t dst = st + (uint32_t)((i >> 1) * 10240 + r * PITCH + c * 16);
            CP_ASYNC16(dst, src);
        }
    };

    float acc[4][4][4];
    #pragma unroll
    for (int mf = 0; mf < 4; mf++)
        #pragma unroll
        for (int nf = 0; nf < 4; nf++)
            #pragma unroll
            for (int j = 0; j < 4; j++) acc[mf][nf][j] = 0.f;

    const int wm = (wid & 1) * 64;
    const int wn = (wid >> 1) * 32;
    // ldmatrix per-thread base offsets (A: x4 over one 16x16 m-frag; B: x4 over two n-frags)
    const uint32_t pA = (uint32_t)((wm + (lane & 15)) * PITCH + (lane >> 4) * 16);
    const int grp = lane >> 3;
    const uint32_t pB = (uint32_t)((wn + (grp >> 1) * 8 + (lane & 7)) * PITCH + (grp & 1) * 16);

    auto compute = [&](uint32_t st) {
        const uint32_t aH = st, aL = st + 10240, bHs = st + 20480, bLs = st + 30720;
        #pragma unroll
        for (int ks = 0; ks < 2; ks++) {
            uint32_t AH[4][4], AL[4][4], BH[4][2], BL[4][2];
            #pragma unroll
            for (int mf = 0; mf < 4; mf++) {
                const uint32_t off = pA + (uint32_t)(mf * 16 * PITCH + ks * 32);
                ldsm_x4(AH[mf], aH + off);
                ldsm_x4(AL[mf], aL + off);
            }
            #pragma unroll
            for (int nf2 = 0; nf2 < 2; nf2++) {
                const uint32_t off = pB + (uint32_t)(nf2 * 16 * PITCH + ks * 32);
                uint32_t t4[4];
                ldsm_x4(t4, bHs + off);
                BH[2*nf2][0] = t4[0]; BH[2*nf2][1] = t4[1];
                BH[2*nf2+1][0] = t4[2]; BH[2*nf2+1][1] = t4[3];
                ldsm_x4(t4, bLs + off);
                BL[2*nf2][0] = t4[0]; BL[2*nf2][1] = t4[1];
                BL[2*nf2+1][0] = t4[2]; BL[2*nf2+1][1] = t4[3];
            }
            #pragma unroll
            for (int mf = 0; mf < 4; mf++)
                #pragma unroll
                for (int nf = 0; nf < 4; nf++) {
                    mma16816(acc[mf][nf], AH[mf], BH[nf]);
                    mma16816(acc[mf][nf], AH[mf], BL[nf]);
                    mma16816(acc[mf][nf], AL[mf], BH[nf]);
                }
        }
    };

    issue(0); CP_COMMIT();
    issue(1); CP_COMMIT();
    issue(2); CP_COMMIT();

    for (int c = 0; c < nchunks; c++) {
        CP_WAIT2();
        __syncthreads();
        compute(sbase + (uint32_t)(c % 3) * STG_SIZE);
        __syncthreads();
        if (c + 3 < nchunks) issue(c + 3);
        CP_COMMIT();
    }
    CP_WAIT0();

    // ---- epilogue ----
    float* Dp = D + (size_t)b * sDb;
    const int er = wm + (lane >> 2);
    const int ec = wn + 2 * (lane & 3);
    if (mode == 0) {
        #pragma unroll
        for (int mf = 0; mf < 4; mf++)
            #pragma unroll
            for (int nf = 0; nf < 4; nf++) {
                size_t base0 = (size_t)(m0 + er + mf * 16) * ldd + (n0 + ec + nf * 8);
                *reinterpret_cast<float2*>(Dp + base0) =
                    make_float2(acc[mf][nf][0], acc[mf][nf][1]);
                *reinterpret_cast<float2*>(Dp + base0 + (size_t)8 * ldd) =
                    make_float2(acc[mf][nf][2], acc[mf][nf][3]);
            }
    } else {
        const float* Gp = gate + (size_t)b * sDb;
        #pragma unroll
        for (int mf = 0; mf < 4; mf++)
            #pragma unroll
            for (int nf = 0; nf < 4; nf++) {
                size_t base0 = (size_t)(m0 + er + mf * 16) * ldd + (n0 + ec + nf * 8);
                float2 g0 = *reinterpret_cast<const float2*>(Gp + base0);
                float2 g1 = *reinterpret_cast<const float2*>(Gp + base0 + (size_t)8 * ldd);
                *reinterpret_cast<float2*>(Dp + base0) =
                    make_float2(g0.x * acc[mf][nf][0], g0.y * acc[mf][nf][1]);
                *reinterpret_cast<float2*>(Dp + base0 + (size_t)8 * ldd) =
                    make_float2(g1.x * acc[mf][nf][2], g1.y * acc[mf][nf][3]);
            }
    }
}

// ---------------- host launch ----------------
extern "C" void kernel_launch(void* const* d_in, const int* in_sizes, int n_in,
                              void* d_out, int out_size) {
    const float* a0 = (const float*)d_in[0];
    const float* a1 = (const float*)d_in[1];
    const float* ctx;
    const float* qry;
    if (in_sizes[0] == BB * LC * DD) { ctx = a0; qry = a1; }
    else                             { ctx = a1; qry = a0; }
    float* out = (float*)d_out;

    void *pChi, *pClo, *pQhi, *pQlo, *pQThi, *pQTlo, *pS, *pAhi, *pAlo;
    cudaGetSymbolAddress(&pChi, g_Chi);   cudaGetSymbolAddress(&pClo, g_Clo);
    cudaGetSymbolAddress(&pQhi, g_Qhi);   cudaGetSymbolAddress(&pQlo, g_Qlo);
    cudaGetSymbolAddress(&pQThi, g_QThi); cudaGetSymbolAddress(&pQTlo, g_QTlo);
    cudaGetSymbolAddress(&pS, g_S);
    cudaGetSymbolAddress(&pAhi, g_Ahi);   cudaGetSymbolAddress(&pAlo, g_Alo);

    cudaFuncSetAttribute(gemm_split_hmma,
                         cudaFuncAttributeMaxDynamicSharedMemorySize, SM_TOTAL);

    // 1) split context into bf16 hi/lo
    {
        int n4 = BB * LC * DD / 4;
        split_kernel<<<(n4 + 255) / 256, 256>>>(ctx, (bf16*)pChi, (bf16*)pClo, n4);
    }
    // 2) split query + transposed copy
    {
        dim3 grid(DD / 32, LQ / 32, BB), blk(32, 8);
        q_split_transpose<<<grid, blk>>>(qry);
    }
    // 3) GEMM1: S_t[c][q] = C . Q^T   (M=LC, N=LQ, K=DD)
    {
        dim3 grid(LQ / 128, LC / 128, BB);   // (4, 16, 8)
        gemm_split_hmma<<<grid, 256, SM_TOTAL>>>(
            (const bf16*)pChi, (const bf16*)pClo, DD, (long)LC * DD,
            (const bf16*)pQhi, (const bf16*)pQlo, DD, (long)LQ * DD,
            DD / 32,
            (float*)pS, LQ, (long)LC * LQ,
            nullptr, 0);
    }
    // 4) softmax over q (rows of S_t) -> alpha hi/lo
    {
        dim3 grid(LC / 8, BB);
        softmax_split_kernel<<<grid, 256>>>();
    }
    // 5) GEMM2 + gate: out[c][d] = ctx[c][d] * (alpha_t . QT^T)  (M=LC, N=DD, K=LQ)
    {
        dim3 grid(DD / 128, LC / 128, BB);   // (6, 16, 8)
        gemm_split_hmma<<<grid, 256, SM_TOTAL>>>(
            (const bf16*)pAhi, (const bf16*)pAlo, LQ, (long)LC * LQ,
            (const bf16*)pQThi, (const bf16*)pQTlo, LQ, (long)DD * LQ,
            LQ / 32,
            out, DD, (long)LC * DD,
            ctx, 1);
    }
}

// round 7
// speedup vs baseline: 2.3694x; 1.1132x over previous
#include <cuda_runtime.h>
#include <cuda_bf16.h>
#include <stdint.h>

typedef __nv_bfloat16 bf16;

#define BB 8
#define LQ 512
#define LC 2048
#define DD 768

// ---------------- scratch (device globals; allocation-free) ----------------
__device__ __align__(128) bf16  g_Chi[BB * LC * DD];
__device__ __align__(128) bf16  g_Clo[BB * LC * DD];
__device__ __align__(128) bf16  g_Qhi[BB * LQ * DD];
__device__ __align__(128) bf16  g_Qlo[BB * LQ * DD];
__device__ __align__(128) bf16  g_QThi[BB * DD * LQ];
__device__ __align__(128) bf16  g_QTlo[BB * DD * LQ];
__device__ __align__(128) float g_S[BB * LC * LQ];      // S_t[b][c][q]
__device__ __align__(128) bf16  g_Ahi[BB * LC * LQ];    // alpha_t hi
__device__ __align__(128) bf16  g_Alo[BB * LC * LQ];    // alpha_t lo

// ---------------- helpers ----------------
__device__ __forceinline__ uint32_t smem_u32(const void* p) {
    uint32_t a;
    asm("{ .reg .u64 t; cvta.to.shared.u64 t, %1; cvt.u32.u64 %0, t; }" : "=r"(a) : "l"(p));
    return a;
}
#define CP_ASYNC16(dst, src) \
    asm volatile("cp.async.cg.shared.global [%0], [%1], 16;" :: "r"(dst), "l"(src))
#define CP_COMMIT() asm volatile("cp.async.commit_group;" ::: "memory")
#define CP_WAIT2()  asm volatile("cp.async.wait_group 2;" ::: "memory")
#define CP_WAIT0()  asm volatile("cp.async.wait_group 0;" ::: "memory")

__device__ __forceinline__ void ldsm_x4(uint32_t* r, uint32_t a) {
    asm volatile("ldmatrix.sync.aligned.m8n8.x4.shared.b16 {%0,%1,%2,%3}, [%4];"
                 : "=r"(r[0]), "=r"(r[1]), "=r"(r[2]), "=r"(r[3]) : "r"(a));
}
__device__ __forceinline__ void mma16816(float* d, const uint32_t* a, const uint32_t* b) {
    asm volatile(
        "mma.sync.aligned.m16n8k16.row.col.f32.bf16.bf16.f32 "
        "{%0,%1,%2,%3}, {%4,%5,%6,%7}, {%8,%9}, {%0,%1,%2,%3};"
        : "+f"(d[0]), "+f"(d[1]), "+f"(d[2]), "+f"(d[3])
        : "r"(a[0]), "r"(a[1]), "r"(a[2]), "r"(a[3]), "r"(b[0]), "r"(b[1]));
}

__device__ __forceinline__ void split_bf16(float x, bf16& hi, bf16& lo) {
    hi = __float2bfloat16(x);
    lo = __float2bfloat16(x - __bfloat162float(hi));
}

// ---------------- kernel: elementwise split (used for C) ----------------
__global__ __launch_bounds__(256)
void split_kernel(const float* __restrict__ x, bf16* __restrict__ hi,
                  bf16* __restrict__ lo, int n4) {
    int i = blockIdx.x * 256 + threadIdx.x;
    if (i >= n4) return;
    float4 v = reinterpret_cast<const float4*>(x)[i];
    bf16 h0, l0, h1, l1, h2, l2, h3, l3;
    split_bf16(v.x, h0, l0); split_bf16(v.y, h1, l1);
    split_bf16(v.z, h2, l2); split_bf16(v.w, h3, l3);
    __nv_bfloat162* h2p = reinterpret_cast<__nv_bfloat162*>(hi) + 2 * i;
    __nv_bfloat162* l2p = reinterpret_cast<__nv_bfloat162*>(lo) + 2 * i;
    h2p[0] = __halves2bfloat162(h0, h1);
    h2p[1] = __halves2bfloat162(h2, h3);
    l2p[0] = __halves2bfloat162(l0, l1);
    l2p[1] = __halves2bfloat162(l2, l3);
}

// ---------------- kernel: Q split + transpose ----------------
__global__ __launch_bounds__(256)
void q_split_transpose(const float* __restrict__ q) {
    __shared__ float tile[32][33];
    int b  = blockIdx.z;
    int d0 = blockIdx.x * 32;
    int q0 = blockIdx.y * 32;
    int tx = threadIdx.x, ty = threadIdx.y;   // 32 x 8

    const float* src = q + ((size_t)b * LQ + q0) * DD + d0;
    #pragma unroll
    for (int i = 0; i < 4; i++) {
        int r = ty + i * 8;
        float v = src[(size_t)r * DD + tx];
        tile[r][tx] = v;
        bf16 h, l; split_bf16(v, h, l);
        size_t idx = ((size_t)b * LQ + q0 + r) * DD + d0 + tx;
        g_Qhi[idx] = h;
        g_Qlo[idx] = l;
    }
    __syncthreads();
    #pragma unroll
    for (int i = 0; i < 4; i++) {
        int r = ty + i * 8;                    // d offset
        float v = tile[tx][r];                 // = Q[q0+tx][d0+r]
        bf16 h, l; split_bf16(v, h, l);
        size_t idx = ((size_t)b * DD + d0 + r) * LQ + q0 + tx;
        g_QThi[idx] = h;
        g_QTlo[idx] = l;
    }
}

// ---------------- kernel: softmax over q (rows of S_t) + bf16 split ----------------
__global__ __launch_bounds__(256)
void softmax_split_kernel() {
    int wid = threadIdx.x >> 5, lane = threadIdx.x & 31;
    int row = blockIdx.x * 8 + wid;            // c index
    int b   = blockIdx.y;
    const float* p = g_S + ((size_t)b * LC + row) * LQ;
    float e[16];
    float m = -3.0e38f;
    #pragma unroll
    for (int i = 0; i < 16; i++) { e[i] = p[lane + i * 32]; m = fmaxf(m, e[i]); }
    #pragma unroll
    for (int off = 16; off; off >>= 1) m = fmaxf(m, __shfl_xor_sync(0xffffffffu, m, off));
    float s = 0.f;
    #pragma unroll
    for (int i = 0; i < 16; i++) { e[i] = expf(e[i] - m); s += e[i]; }
    #pragma unroll
    for (int off = 16; off; off >>= 1) s += __shfl_xor_sync(0xffffffffu, s, off);
    float inv = 1.0f / s;
    bf16* ah = g_Ahi + ((size_t)b * LC + row) * LQ;
    bf16* al = g_Alo + ((size_t)b * LC + row) * LQ;
    #pragma unroll
    for (int i = 0; i < 16; i++) {
        float a = e[i] * inv;
        bf16 h, l; split_bf16(a, h, l);
        ah[lane + i * 32] = h;
        al[lane + i * 32] = l;
    }
}

// ---------------- unified split-precision HMMA GEMM (+gating epilogue) --------
// D[m][n] = sum_k A[m][k]*B[n][k], computed as Ah*Bh + Ah*Bl + Al*Bh, fp32 acc.
// Block tile 128x128, 8 warps (2m x 4n), warp tile 64x32, KC=32, 4-stage cp.async,
// ONE barrier per chunk. MMAs are term-major so consecutive MMAs never share an
// accumulator (dependency distance 16 — hides HMMA latency).
#define PITCH    80        // 32 k (64B) + 16B pad -> conflict-free ldmatrix
#define STG_SIZE 40960     // 4 arrays * 128 rows * 80B
#define NSTG     4
#define SM_TOTAL (NSTG * STG_SIZE)   // 163840

__global__ __launch_bounds__(256, 1)
void gemm_split_hmma(const bf16* __restrict__ Ah, const bf16* __restrict__ Al,
                     int lda, long sAb,
                     const bf16* __restrict__ Bh, const bf16* __restrict__ Bl,
                     int ldb, long sBb,
                     int nchunks,
                     float* __restrict__ D, int ldd, long sDb,
                     const float* __restrict__ gate, int mode) {
    extern __shared__ char smem[];
    const uint32_t sbase = smem_u32(smem);
    const int tid = threadIdx.x, wid = tid >> 5, lane = tid & 31;
    const int b  = blockIdx.z;
    const int m0 = blockIdx.y * 128, n0 = blockIdx.x * 128;

    const bf16* Ahp = Ah + (size_t)b * sAb + (size_t)m0 * lda;
    const bf16* Alp = Al + (size_t)b * sAb + (size_t)m0 * lda;
    const bf16* Bhp = Bh + (size_t)b * sBb + (size_t)n0 * ldb;
    const bf16* Blp = Bl + (size_t)b * sBb + (size_t)n0 * ldb;

    // cp.async issue for one 32-k chunk into stage (chunk % NSTG).
    auto issue = [&](int chunk) {
        const uint32_t st = sbase + (uint32_t)(chunk % NSTG) * STG_SIZE;
        const int k0 = chunk * 32;
        #pragma unroll
        for (int i = 0; i < 8; i++) {                    // i>>1: 0=Ah 1=Al 2=Bh 3=Bl
            const int u = i * 256 + tid;
            const int r = (u >> 2) & 127;
            const int c = u & 3;
            const bf16* base = (i < 2) ? Ahp : (i < 4) ? Alp : (i < 6) ? Bhp : Blp;
            const int ld = (i < 4) ? lda : ldb;
            const bf16* src = base + (size_t)r * ld + k0 + c * 8;
            const uint32_t dst = st + (uint32_t)((i >> 1) * 10240 + r * PITCH + c * 16);
            CP_ASYNC16(dst, src);
        }
    };

    float acc[4][4][4];
    #pragma unroll
    for (int mf = 0; mf < 4; mf++)
        #pragma unroll
        for (int nf = 0; nf < 4; nf++)
            #pragma unroll
            for (int j = 0; j < 4; j++) acc[mf][nf][j] = 0.f;

    const int wm = (wid & 1) * 64;
    const int wn = (wid >> 1) * 32;
    // ldmatrix per-thread base offsets (A: x4 over one 16x16 m-frag; B: x4 over two n-frags)
    const uint32_t pA = (uint32_t)((wm + (lane & 15)) * PITCH + (lane >> 4) * 16);
    const int grp = lane >> 3;
    const uint32_t pB = (uint32_t)((wn + (grp >> 1) * 8 + (lane & 7)) * PITCH + (grp & 1) * 16);

    auto compute = [&](uint32_t st) {
        const uint32_t aH = st, aL = st + 10240, bHs = st + 20480, bLs = st + 30720;
        #pragma unroll
        for (int ks = 0; ks < 2; ks++) {
            uint32_t AH[4][4], AL[4][4], BH[4][2], BL[4][2];
            #pragma unroll
            for (int mf = 0; mf < 4; mf++) {
                const uint32_t off = pA + (uint32_t)(mf * 16 * PITCH + ks * 32);
                ldsm_x4(AH[mf], aH + off);
                ldsm_x4(AL[mf], aL + off);
            }
            #pragma unroll
            for (int nf2 = 0; nf2 < 2; nf2++) {
                const uint32_t off = pB + (uint32_t)(nf2 * 16 * PITCH + ks * 32);
                uint32_t t4[4];
                ldsm_x4(t4, bHs + off);
                BH[2*nf2][0] = t4[0]; BH[2*nf2][1] = t4[1];
                BH[2*nf2+1][0] = t4[2]; BH[2*nf2+1][1] = t4[3];
                ldsm_x4(t4, bLs + off);
                BL[2*nf2][0] = t4[0]; BL[2*nf2][1] = t4[1];
                BL[2*nf2+1][0] = t4[2]; BL[2*nf2+1][1] = t4[3];
            }
            // Term-major: 16 independent accumulators between reuses of any acc.
            #pragma unroll
            for (int mf = 0; mf < 4; mf++)
                #pragma unroll
                for (int nf = 0; nf < 4; nf++)
                    mma16816(acc[mf][nf], AH[mf], BH[nf]);
            #pragma unroll
            for (int mf = 0; mf < 4; mf++)
                #pragma unroll
                for (int nf = 0; nf < 4; nf++)
                    mma16816(acc[mf][nf], AH[mf], BL[nf]);
            #pragma unroll
            for (int mf = 0; mf < 4; mf++)
                #pragma unroll
                for (int nf = 0; nf < 4; nf++)
                    mma16816(acc[mf][nf], AL[mf], BH[nf]);
        }
    };

    issue(0); CP_COMMIT();
    issue(1); CP_COMMIT();
    issue(2); CP_COMMIT();

    for (int c = 0; c < nchunks; c++) {
        CP_WAIT2();
        __syncthreads();   // all threads' stage-c data visible block-wide
        compute(sbase + (uint32_t)(c % NSTG) * STG_SIZE);
        // Write stage (c+3)%NSTG: with NSTG=4 it differs from stage c%NSTG that
        // slower warps may still be reading, and from the two stages in flight.
        if (c + 3 < nchunks) issue(c + 3);
        CP_COMMIT();
    }
    CP_WAIT0();

    // ---- epilogue ----
    float* Dp = D + (size_t)b * sDb;
    const int er = wm + (lane >> 2);
    const int ec = wn + 2 * (lane & 3);
    if (mode == 0) {
        #pragma unroll
        for (int mf = 0; mf < 4; mf++)
            #pragma unroll
            for (int nf = 0; nf < 4; nf++) {
                size_t base0 = (size_t)(m0 + er + mf * 16) * ldd + (n0 + ec + nf * 8);
                *reinterpret_cast<float2*>(Dp + base0) =
                    make_float2(acc[mf][nf][0], acc[mf][nf][1]);
                *reinterpret_cast<float2*>(Dp + base0 + (size_t)8 * ldd) =
                    make_float2(acc[mf][nf][2], acc[mf][nf][3]);
            }
    } else {
        const float* Gp = gate + (size_t)b * sDb;
        #pragma unroll
        for (int mf = 0; mf < 4; mf++)
            #pragma unroll
            for (int nf = 0; nf < 4; nf++) {
                size_t base0 = (size_t)(m0 + er + mf * 16) * ldd + (n0 + ec + nf * 8);
                float2 g0 = *reinterpret_cast<const float2*>(Gp + base0);
                float2 g1 = *reinterpret_cast<const float2*>(Gp + base0 + (size_t)8 * ldd);
                *reinterpret_cast<float2*>(Dp + base0) =
                    make_float2(g0.x * acc[mf][nf][0], g0.y * acc[mf][nf][1]);
                *reinterpret_cast<float2*>(Dp + base0 + (size_t)8 * ldd) =
                    make_float2(g1.x * acc[mf][nf][2], g1.y * acc[mf][nf][3]);
            }
    }
}

// ---------------- host launch ----------------
extern "C" void kernel_launch(void* const* d_in, const int* in_sizes, int n_in,
                              void* d_out, int out_size) {
    const float* a0 = (const float*)d_in[0];
    const float* a1 = (const float*)d_in[1];
    const float* ctx;
    const float* qry;
    if (in_sizes[0] == BB * LC * DD) { ctx = a0; qry = a1; }
    else                             { ctx = a1; qry = a0; }
    float* out = (float*)d_out;

    void *pChi, *pClo, *pQhi, *pQlo, *pQThi, *pQTlo, *pS, *pAhi, *pAlo;
    cudaGetSymbolAddress(&pChi, g_Chi);   cudaGetSymbolAddress(&pClo, g_Clo);
    cudaGetSymbolAddress(&pQhi, g_Qhi);   cudaGetSymbolAddress(&pQlo, g_Qlo);
    cudaGetSymbolAddress(&pQThi, g_QThi); cudaGetSymbolAddress(&pQTlo, g_QTlo);
    cudaGetSymbolAddress(&pS, g_S);
    cudaGetSymbolAddress(&pAhi, g_Ahi);   cudaGetSymbolAddress(&pAlo, g_Alo);

    cudaFuncSetAttribute(gemm_split_hmma,
                         cudaFuncAttributeMaxDynamicSharedMemorySize, SM_TOTAL);

    // 1) split context into bf16 hi/lo
    {
        int n4 = BB * LC * DD / 4;
        split_kernel<<<(n4 + 255) / 256, 256>>>(ctx, (bf16*)pChi, (bf16*)pClo, n4);
    }
    // 2) split query + transposed copy
    {
        dim3 grid(DD / 32, LQ / 32, BB), blk(32, 8);
        q_split_transpose<<<grid, blk>>>(qry);
    }
    // 3) GEMM1: S_t[c][q] = C . Q^T   (M=LC, N=LQ, K=DD)
    {
        dim3 grid(LQ / 128, LC / 128, BB);   // (4, 16, 8)
        gemm_split_hmma<<<grid, 256, SM_TOTAL>>>(
            (const bf16*)pChi, (const bf16*)pClo, DD, (long)LC * DD,
            (const bf16*)pQhi, (const bf16*)pQlo, DD, (long)LQ * DD,
            DD / 32,
            (float*)pS, LQ, (long)LC * LQ,
            nullptr, 0);
    }
    // 4) softmax over q (rows of S_t) -> alpha hi/lo
    {
        dim3 grid(LC / 8, BB);
        softmax_split_kernel<<<grid, 256>>>();
    }
    // 5) GEMM2 + gate: out[c][d] = ctx[c][d] * (alpha_t . QT^T)  (M=LC, N=DD, K=LQ)
    {
        dim3 grid(DD / 128, LC / 128, BB);   // (6, 16, 8)
        gemm_split_hmma<<<grid, 256, SM_TOTAL>>>(
            (const bf16*)pAhi, (const bf16*)pAlo, LQ, (long)LC * LQ,
            (const bf16*)pQThi, (const bf16*)pQTlo, LQ, (long)DD * LQ,
            LQ / 32,
            out, DD, (long)LC * DD,
            ctx, 1);
    }
}

// round 8
// speedup vs baseline: 3.5821x; 1.5118x over previous
#include <cuda_runtime.h>
#include <cuda_bf16.h>
#include <stdint.h>

typedef __nv_bfloat16 bf16;

#define BB 8
#define LQ 512
#define LC 2048
#define DD 768

// ---------------- scratch (device globals; allocation-free) ----------------
__device__ __align__(128) bf16  g_Chi[BB * LC * DD];
__device__ __align__(128) bf16  g_Clo[BB * LC * DD];
__device__ __align__(128) bf16  g_Qhi[BB * LQ * DD];
__device__ __align__(128) bf16  g_Qlo[BB * LQ * DD];
__device__ __align__(128) float g_S[BB * LC * LQ];      // S_t[b][c][q]

// ---------------- helpers ----------------
__device__ __forceinline__ uint32_t smem_u32(const void* p) {
    uint32_t a;
    asm("{ .reg .u64 t; cvta.to.shared.u64 t, %1; cvt.u32.u64 %0, t; }" : "=r"(a) : "l"(p));
    return a;
}
#define CP_ASYNC16(dst, src) \
    asm volatile("cp.async.cg.shared.global [%0], [%1], 16;" :: "r"(dst), "l"(src))
#define CP_COMMIT() asm volatile("cp.async.commit_group;" ::: "memory")
#define CP_WAIT2()  asm volatile("cp.async.wait_group 2;" ::: "memory")
#define CP_WAIT0()  asm volatile("cp.async.wait_group 0;" ::: "memory")

__device__ __forceinline__ void ldsm_x4(uint32_t* r, uint32_t a) {
    asm volatile("ldmatrix.sync.aligned.m8n8.x4.shared.b16 {%0,%1,%2,%3}, [%4];"
                 : "=r"(r[0]), "=r"(r[1]), "=r"(r[2]), "=r"(r[3]) : "r"(a));
}
__device__ __forceinline__ void mma16816(float* d, const uint32_t* a, const uint32_t* b) {
    asm volatile(
        "mma.sync.aligned.m16n8k16.row.col.f32.bf16.bf16.f32 "
        "{%0,%1,%2,%3}, {%4,%5,%6,%7}, {%8,%9}, {%0,%1,%2,%3};"
        : "+f"(d[0]), "+f"(d[1]), "+f"(d[2]), "+f"(d[3])
        : "r"(a[0]), "r"(a[1]), "r"(a[2]), "r"(a[3]), "r"(b[0]), "r"(b[1]));
}

__device__ __forceinline__ void split_bf16(float x, bf16& hi, bf16& lo) {
    hi = __float2bfloat16(x);
    lo = __float2bfloat16(x - __bfloat162float(hi));
}

// ---------------- kernel: elementwise split (C and Q) ----------------
__global__ __launch_bounds__(256)
void split_kernel(const float* __restrict__ x, bf16* __restrict__ hi,
                  bf16* __restrict__ lo, int n4) {
    int i = blockIdx.x * 256 + threadIdx.x;
    if (i >= n4) return;
    float4 v = reinterpret_cast<const float4*>(x)[i];
    bf16 h0, l0, h1, l1, h2, l2, h3, l3;
    split_bf16(v.x, h0, l0); split_bf16(v.y, h1, l1);
    split_bf16(v.z, h2, l2); split_bf16(v.w, h3, l3);
    __nv_bfloat162* h2p = reinterpret_cast<__nv_bfloat162*>(hi) + 2 * i;
    __nv_bfloat162* l2p = reinterpret_cast<__nv_bfloat162*>(lo) + 2 * i;
    h2p[0] = __halves2bfloat162(h0, h1);
    h2p[1] = __halves2bfloat162(h2, h3);
    l2p[0] = __halves2bfloat162(l0, l1);
    l2p[1] = __halves2bfloat162(l2, l3);
}

// ---------------- split-precision HMMA GEMM1 (unchanged mainloop) ------------
// S_t[c][q] = sum_d C[c,d]*Q[q,d], computed as ChQh + ChQl + ClQh, fp32 acc.
// Block tile 128x128, 8 warps (2m x 4n), warp tile 64x32, KC=32, 4-stage cp.async.
#define PITCH    80
#define STG_SIZE 40960
#define NSTG     4
#define SM_TOTAL (NSTG * STG_SIZE)   // 163840

__global__ __launch_bounds__(256, 1)
void gemm_split_hmma(const bf16* __restrict__ Ah, const bf16* __restrict__ Al,
                     int lda, long sAb,
                     const bf16* __restrict__ Bh, const bf16* __restrict__ Bl,
                     int ldb, long sBb,
                     int nchunks,
                     float* __restrict__ D, int ldd, long sDb) {
    extern __shared__ char smem[];
    const uint32_t sbase = smem_u32(smem);
    const int tid = threadIdx.x, wid = tid >> 5, lane = tid & 31;
    const int b  = blockIdx.z;
    const int m0 = blockIdx.y * 128, n0 = blockIdx.x * 128;

    const bf16* Ahp = Ah + (size_t)b * sAb + (size_t)m0 * lda;
    const bf16* Alp = Al + (size_t)b * sAb + (size_t)m0 * lda;
    const bf16* Bhp = Bh + (size_t)b * sBb + (size_t)n0 * ldb;
    const bf16* Blp = Bl + (size_t)b * sBb + (size_t)n0 * ldb;

    auto issue = [&](int chunk) {
        const uint32_t st = sbase + (uint32_t)(chunk % NSTG) * STG_SIZE;
        const int k0 = chunk * 32;
        #pragma unroll
        for (int i = 0; i < 8; i++) {
            const int u = i * 256 + tid;
            const int r = (u >> 2) & 127;
            const int c = u & 3;
            const bf16* base = (i < 2) ? Ahp : (i < 4) ? Alp : (i < 6) ? Bhp : Blp;
            const int ld = (i < 4) ? lda : ldb;
            const bf16* src = base + (size_t)r * ld + k0 + c * 8;
            const uint32_t dst = st + (uint32_t)((i >> 1) * 10240 + r * PITCH + c * 16);
            CP_ASYNC16(dst, src);
        }
    };

    float acc[4][4][4];
    #pragma unroll
    for (int mf = 0; mf < 4; mf++)
        #pragma unroll
        for (int nf = 0; nf < 4; nf++)
            #pragma unroll
            for (int j = 0; j < 4; j++) acc[mf][nf][j] = 0.f;

    const int wm = (wid & 1) * 64;
    const int wn = (wid >> 1) * 32;
    const uint32_t pA = (uint32_t)((wm + (lane & 15)) * PITCH + (lane >> 4) * 16);
    const int grp = lane >> 3;
    const uint32_t pB = (uint32_t)((wn + (grp >> 1) * 8 + (lane & 7)) * PITCH + (grp & 1) * 16);

    auto compute = [&](uint32_t st) {
        const uint32_t aH = st, aL = st + 10240, bHs = st + 20480, bLs = st + 30720;
        #pragma unroll
        for (int ks = 0; ks < 2; ks++) {
            uint32_t AH[4][4], AL[4][4], BH[4][2], BL[4][2];
            #pragma unroll
            for (int mf = 0; mf < 4; mf++) {
                const uint32_t off = pA + (uint32_t)(mf * 16 * PITCH + ks * 32);
                ldsm_x4(AH[mf], aH + off);
                ldsm_x4(AL[mf], aL + off);
            }
            #pragma unroll
            for (int nf2 = 0; nf2 < 2; nf2++) {
                const uint32_t off = pB + (uint32_t)(nf2 * 16 * PITCH + ks * 32);
                uint32_t t4[4];
                ldsm_x4(t4, bHs + off);
                BH[2*nf2][0] = t4[0]; BH[2*nf2][1] = t4[1];
                BH[2*nf2+1][0] = t4[2]; BH[2*nf2+1][1] = t4[3];
                ldsm_x4(t4, bLs + off);
                BL[2*nf2][0] = t4[0]; BL[2*nf2][1] = t4[1];
                BL[2*nf2+1][0] = t4[2]; BL[2*nf2+1][1] = t4[3];
            }
            #pragma unroll
            for (int mf = 0; mf < 4; mf++)
                #pragma unroll
                for (int nf = 0; nf < 4; nf++)
                    mma16816(acc[mf][nf], AH[mf], BH[nf]);
            #pragma unroll
            for (int mf = 0; mf < 4; mf++)
                #pragma unroll
                for (int nf = 0; nf < 4; nf++)
                    mma16816(acc[mf][nf], AH[mf], BL[nf]);
            #pragma unroll
            for (int mf = 0; mf < 4; mf++)
                #pragma unroll
                for (int nf = 0; nf < 4; nf++)
                    mma16816(acc[mf][nf], AL[mf], BH[nf]);
        }
    };

    issue(0); CP_COMMIT();
    issue(1); CP_COMMIT();
    issue(2); CP_COMMIT();

    for (int c = 0; c < nchunks; c++) {
        CP_WAIT2();
        __syncthreads();
        compute(sbase + (uint32_t)(c % NSTG) * STG_SIZE);
        if (c + 3 < nchunks) issue(c + 3);
        CP_COMMIT();
    }
    CP_WAIT0();

    // ---- epilogue (plain store) ----
    float* Dp = D + (size_t)b * sDb;
    const int er = wm + (lane >> 2);
    const int ec = wn + 2 * (lane & 3);
    #pragma unroll
    for (int mf = 0; mf < 4; mf++)
        #pragma unroll
        for (int nf = 0; nf < 4; nf++) {
            size_t base0 = (size_t)(m0 + er + mf * 16) * ldd + (n0 + ec + nf * 8);
            *reinterpret_cast<float2*>(Dp + base0) =
                make_float2(acc[mf][nf][0], acc[mf][nf][1]);
            *reinterpret_cast<float2*>(Dp + base0 + (size_t)8 * ldd) =
                make_float2(acc[mf][nf][2], acc[mf][nf][3]);
        }
}

// ---------------- fused: softmax over q + sparse AWQ gather + gate -----------
// One warp per c-row. alpha = softmax_q(S[:,c]) is near-one-hot (logit std ~28):
// entries with e = exp(S - max) <= 1.5e-8 contribute <= 512*1.5e-8 < 1e-5 of the
// mass REGARDLESS of data, so only surviving q's are gathered (exact fp32 FFMA).
// Adversarial data only slows this kernel down; it never breaks correctness.
__global__ __launch_bounds__(256)
void softmax_awq_gate(const float* __restrict__ qry,
                      const float* __restrict__ ctx,
                      float* __restrict__ out) {
    const int wid = threadIdx.x >> 5, lane = threadIdx.x & 31;
    const int c = blockIdx.x * 8 + wid;
    const int b = blockIdx.y;

    const float* Srow = g_S + ((size_t)b * LC + c) * LQ;

    float e[16];
    float m = -3.0e38f;
    #pragma unroll
    for (int i = 0; i < 16; i++) { e[i] = Srow[lane + 32 * i]; m = fmaxf(m, e[i]); }
    #pragma unroll
    for (int off = 16; off; off >>= 1)
        m = fmaxf(m, __shfl_xor_sync(0xffffffffu, m, off));

    float Z = 0.f;
    #pragma unroll
    for (int i = 0; i < 16; i++) { e[i] = __expf(e[i] - m); Z += e[i]; }
    #pragma unroll
    for (int off = 16; off; off >>= 1)
        Z += __shfl_xor_sync(0xffffffffu, Z, off);

    float acc[24];
    #pragma unroll
    for (int j = 0; j < 24; j++) acc[j] = 0.f;

    const float* Qb = qry + (size_t)b * LQ * DD;
    const float TH = 1.523e-8f;   // exp(-18)
    #pragma unroll
    for (int i = 0; i < 16; i++) {
        unsigned mask = __ballot_sync(0xffffffffu, e[i] > TH);
        while (mask) {
            const int bit = __ffs(mask) - 1;
            mask &= mask - 1;
            const float w = __shfl_sync(0xffffffffu, e[i], bit);
            const float* Qr = Qb + (size_t)(i * 32 + bit) * DD;
            #pragma unroll
            for (int j = 0; j < 24; j++)
                acc[j] = fmaf(w, Qr[lane + 32 * j], acc[j]);
        }
    }

    const float invZ = 1.0f / Z;
    const float* Crow = ctx + ((size_t)b * LC + c) * DD;
    float*       Orow = out + ((size_t)b * LC + c) * DD;
    #pragma unroll
    for (int j = 0; j < 24; j++)
        Orow[lane + 32 * j] = Crow[lane + 32 * j] * (acc[j] * invZ);
}

// ---------------- host launch ----------------
extern "C" void kernel_launch(void* const* d_in, const int* in_sizes, int n_in,
                              void* d_out, int out_size) {
    const float* a0 = (const float*)d_in[0];
    const float* a1 = (const float*)d_in[1];
    const float* ctx;
    const float* qry;
    if (in_sizes[0] == BB * LC * DD) { ctx = a0; qry = a1; }
    else                             { ctx = a1; qry = a0; }
    float* out = (float*)d_out;

    void *pChi, *pClo, *pQhi, *pQlo, *pS;
    cudaGetSymbolAddress(&pChi, g_Chi); cudaGetSymbolAddress(&pClo, g_Clo);
    cudaGetSymbolAddress(&pQhi, g_Qhi); cudaGetSymbolAddress(&pQlo, g_Qlo);
    cudaGetSymbolAddress(&pS, g_S);

    cudaFuncSetAttribute(gemm_split_hmma,
                         cudaFuncAttributeMaxDynamicSharedMemorySize, SM_TOTAL);

    // 1) split context into bf16 hi/lo
    {
        int n4 = BB * LC * DD / 4;
        split_kernel<<<(n4 + 255) / 256, 256>>>(ctx, (bf16*)pChi, (bf16*)pClo, n4);
    }
    // 2) split query into bf16 hi/lo (no transpose needed anymore)
    {
        int n4 = BB * LQ * DD / 4;
        split_kernel<<<(n4 + 255) / 256, 256>>>(qry, (bf16*)pQhi, (bf16*)pQlo, n4);
    }
    // 3) GEMM1: S_t[c][q] = C . Q^T   (M=LC, N=LQ, K=DD)
    {
        dim3 grid(LQ / 128, LC / 128, BB);   // (4, 16, 8)
        gemm_split_hmma<<<grid, 256, SM_TOTAL>>>(
            (const bf16*)pChi, (const bf16*)pClo, DD, (long)LC * DD,
            (const bf16*)pQhi, (const bf16*)pQlo, DD, (long)LQ * DD,
            DD / 32,
            (float*)pS, LQ, (long)LC * LQ);
    }
    // 4) fused softmax + sparse AWQ gather + gate (replaces GEMM2 entirely)
    {
        dim3 grid(LC / 8, BB);
        softmax_awq_gate<<<grid, 256>>>(qry, ctx, out);
    }
}

// round 9
// speedup vs baseline: 4.7777x; 1.3338x over previous
#include <cuda_runtime.h>
#include <cuda_bf16.h>
#include <stdint.h>

typedef __nv_bfloat16 bf16;

#define BB 8
#define LQ 512
#define LC 2048
#define DD 768

// ---------------- scratch (device globals; allocation-free) ----------------
__device__ __align__(128) bf16 g_Chi[BB * LC * DD];
__device__ __align__(128) bf16 g_Qhi[BB * LQ * DD];
__device__ __align__(128) bf16 g_S[BB * LC * LQ];   // approximate logits S_t[b][c][q]

// ---------------- helpers ----------------
__device__ __forceinline__ uint32_t smem_u32(const void* p) {
    uint32_t a;
    asm("{ .reg .u64 t; cvta.to.shared.u64 t, %1; cvt.u32.u64 %0, t; }" : "=r"(a) : "l"(p));
    return a;
}
#define CP_ASYNC16(dst, src) \
    asm volatile("cp.async.cg.shared.global [%0], [%1], 16;" :: "r"(dst), "l"(src))
#define CP_COMMIT() asm volatile("cp.async.commit_group;" ::: "memory")
#define CP_WAIT2()  asm volatile("cp.async.wait_group 2;" ::: "memory")
#define CP_WAIT0()  asm volatile("cp.async.wait_group 0;" ::: "memory")

__device__ __forceinline__ void ldsm_x4(uint32_t* r, uint32_t a) {
    asm volatile("ldmatrix.sync.aligned.m8n8.x4.shared.b16 {%0,%1,%2,%3}, [%4];"
                 : "=r"(r[0]), "=r"(r[1]), "=r"(r[2]), "=r"(r[3]) : "r"(a));
}
__device__ __forceinline__ void mma16816(float* d, const uint32_t* a, const uint32_t* b) {
    asm volatile(
        "mma.sync.aligned.m16n8k16.row.col.f32.bf16.bf16.f32 "
        "{%0,%1,%2,%3}, {%4,%5,%6,%7}, {%8,%9}, {%0,%1,%2,%3};"
        : "+f"(d[0]), "+f"(d[1]), "+f"(d[2]), "+f"(d[3])
        : "r"(a[0]), "r"(a[1]), "r"(a[2]), "r"(a[3]), "r"(b[0]), "r"(b[1]));
}

// ---------------- kernel: fp32 -> bf16 convert ----------------
__global__ __launch_bounds__(256)
void to_bf16_kernel(const float* __restrict__ x, bf16* __restrict__ hi, int n4) {
    int i = blockIdx.x * 256 + threadIdx.x;
    if (i >= n4) return;
    float4 v = reinterpret_cast<const float4*>(x)[i];
    __nv_bfloat162* h2p = reinterpret_cast<__nv_bfloat162*>(hi) + 2 * i;
    h2p[0] = __floats2bfloat162_rn(v.x, v.y);
    h2p[1] = __floats2bfloat162_rn(v.z, v.w);
}

// ---------------- 1-term bf16 HMMA screening GEMM ----------------
// S_approx[c][q] = sum_d Chi[c,d]*Qhi[q,d], fp32 acc, stored bf16.
// Block tile 128x128, 8 warps (2m x 4n), warp tile 64x32, KC=32, 4-stage cp.async.
#define PITCH    80
#define STG_SIZE 20480      // 2 arrays * 128 rows * 80B
#define NSTG     4
#define SM_TOTAL (NSTG * STG_SIZE)   // 81920 -> 2 CTAs/SM

__global__ __launch_bounds__(256, 2)
void gemm_hh(const bf16* __restrict__ A, int lda, long sAb,
             const bf16* __restrict__ B, int ldb, long sBb,
             int nchunks,
             bf16* __restrict__ D, int ldd, long sDb) {
    extern __shared__ char smem[];
    const uint32_t sbase = smem_u32(smem);
    const int tid = threadIdx.x, wid = tid >> 5, lane = tid & 31;
    const int b  = blockIdx.z;
    const int m0 = blockIdx.y * 128, n0 = blockIdx.x * 128;

    const bf16* Ap = A + (size_t)b * sAb + (size_t)m0 * lda;
    const bf16* Bp = B + (size_t)b * sBb + (size_t)n0 * ldb;

    auto issue = [&](int chunk) {
        const uint32_t st = sbase + (uint32_t)(chunk % NSTG) * STG_SIZE;
        const int k0 = chunk * 32;
        #pragma unroll
        for (int i = 0; i < 4; i++) {           // 1024 16B units: A then B
            const int u = i * 256 + tid;
            const int r = (u >> 2) & 127;
            const int c = u & 3;
            const bf16* base = (i < 2) ? Ap : Bp;
            const int ld = (i < 2) ? lda : ldb;
            const bf16* src = base + (size_t)r * ld + k0 + c * 8;
            const uint32_t dst = st + (uint32_t)((i < 2 ? 0 : 10240) + r * PITCH + c * 16);
            CP_ASYNC16(dst, src);
        }
    };

    float acc[4][4][4];
    #pragma unroll
    for (int mf = 0; mf < 4; mf++)
        #pragma unroll
        for (int nf = 0; nf < 4; nf++)
            #pragma unroll
            for (int j = 0; j < 4; j++) acc[mf][nf][j] = 0.f;

    const int wm = (wid & 1) * 64;
    const int wn = (wid >> 1) * 32;
    const uint32_t pA = (uint32_t)((wm + (lane & 15)) * PITCH + (lane >> 4) * 16);
    const int grp = lane >> 3;
    const uint32_t pB = (uint32_t)((wn + (grp >> 1) * 8 + (lane & 7)) * PITCH + (grp & 1) * 16);

    auto compute = [&](uint32_t st) {
        const uint32_t aS = st, bS = st + 10240;
        #pragma unroll
        for (int ks = 0; ks < 2; ks++) {
            uint32_t AF[4][4], BF[4][2];
            #pragma unroll
            for (int mf = 0; mf < 4; mf++)
                ldsm_x4(AF[mf], aS + pA + (uint32_t)(mf * 16 * PITCH + ks * 32));
            #pragma unroll
            for (int nf2 = 0; nf2 < 2; nf2++) {
                uint32_t t4[4];
                ldsm_x4(t4, bS + pB + (uint32_t)(nf2 * 16 * PITCH + ks * 32));
                BF[2*nf2][0] = t4[0]; BF[2*nf2][1] = t4[1];
                BF[2*nf2+1][0] = t4[2]; BF[2*nf2+1][1] = t4[3];
            }
            #pragma unroll
            for (int mf = 0; mf < 4; mf++)
                #pragma unroll
                for (int nf = 0; nf < 4; nf++)
                    mma16816(acc[mf][nf], AF[mf], BF[nf]);
        }
    };

    issue(0); CP_COMMIT();
    issue(1); CP_COMMIT();
    issue(2); CP_COMMIT();

    for (int c = 0; c < nchunks; c++) {
        CP_WAIT2();
        __syncthreads();
        compute(sbase + (uint32_t)(c % NSTG) * STG_SIZE);
        if (c + 3 < nchunks) issue(c + 3);
        CP_COMMIT();
    }
    CP_WAIT0();

    // epilogue: store bf16
    bf16* Dp = D + (size_t)b * sDb;
    const int er = wm + (lane >> 2);
    const int ec = wn + 2 * (lane & 3);
    #pragma unroll
    for (int mf = 0; mf < 4; mf++)
        #pragma unroll
        for (int nf = 0; nf < 4; nf++) {
            size_t base0 = (size_t)(m0 + er + mf * 16) * ldd + (n0 + ec + nf * 8);
            *reinterpret_cast<__nv_bfloat162*>(Dp + base0) =
                __floats2bfloat162_rn(acc[mf][nf][0], acc[mf][nf][1]);
            *reinterpret_cast<__nv_bfloat162*>(Dp + base0 + (size_t)8 * ldd) =
                __floats2bfloat162_rn(acc[mf][nf][2], acc[mf][nf][3]);
        }
}

// ---------------- fused: candidate select + exact logits + online softmax AWQ + gate
// One warp per c-row. S_approx screens candidates within WINDOW of the row max
// (WINDOW=23 covers softmax mass cutoff 18.4 + screen error + bf16 quantization).
// Candidates get exact fp32 dot products; online-softmax accumulation means each
// gathered Q row is loaded once. All softmax math on exact logits -> high accuracy.
__global__ __launch_bounds__(256)
void softmax_awq_gate(const float* __restrict__ qry,
                      const float* __restrict__ ctx,
                      float* __restrict__ out) {
    const int wid = threadIdx.x >> 5, lane = threadIdx.x & 31;
    const int c = blockIdx.x * 8 + wid;
    const int b = blockIdx.y;

    // approximate scores: 512 bf16 = 256 bf16x2; 8 pairs per lane
    const __nv_bfloat162* S2 =
        reinterpret_cast<const __nv_bfloat162*>(g_S + ((size_t)b * LC + c) * LQ);
    float sv[16];
    float m = -3.0e38f;
    #pragma unroll
    for (int i = 0; i < 8; i++) {
        float2 v = __bfloat1622float2(S2[lane + 32 * i]);
        sv[2 * i]     = v.x;
        sv[2 * i + 1] = v.y;
        m = fmaxf(m, fmaxf(v.x, v.y));
    }
    #pragma unroll
    for (int off = 16; off; off >>= 1)
        m = fmaxf(m, __shfl_xor_sync(0xffffffffu, m, off));

    // context row (reused: exact dots + gating)
    const float4* C4 = reinterpret_cast<const float4*>(ctx + ((size_t)b * LC + c) * DD);
    float4 cv[6];
    #pragma unroll
    for (int j = 0; j < 6; j++) cv[j] = C4[lane + 32 * j];

    const float thr = m - 23.0f;
    float M = -3.0e38f, Z = 0.f;
    float4 acc[6];
    #pragma unroll
    for (int j = 0; j < 6; j++) acc[j] = make_float4(0.f, 0.f, 0.f, 0.f);

    const float* Qb = qry + (size_t)b * LQ * DD;
    #pragma unroll
    for (int k = 0; k < 16; k++) {
        unsigned mask = __ballot_sync(0xffffffffu, sv[k] > thr);
        while (mask) {
            const int bit = __ffs(mask) - 1;
            mask &= mask - 1;
            const int q = 2 * bit + 64 * (k >> 1) + (k & 1);
            const float4* Q4 = reinterpret_cast<const float4*>(Qb + (size_t)q * DD);
            float4 qv[6];
            #pragma unroll
            for (int j = 0; j < 6; j++) qv[j] = Q4[lane + 32 * j];
            // exact fp32 dot C[c,:] . Q[q,:]
            float d = 0.f;
            #pragma unroll
            for (int j = 0; j < 6; j++)
                d += cv[j].x * qv[j].x + cv[j].y * qv[j].y +
                     cv[j].z * qv[j].z + cv[j].w * qv[j].w;
            #pragma unroll
            for (int off = 16; off; off >>= 1)
                d += __shfl_xor_sync(0xffffffffu, d, off);
            // online softmax update (uniform across warp)
            const float Mn = fmaxf(M, d);
            const float scale = __expf(M - Mn);   // first iter: exp(-3e38)=0
            const float w = __expf(d - Mn);
            Z = Z * scale + w;
            #pragma unroll
            for (int j = 0; j < 6; j++) {
                acc[j].x = acc[j].x * scale + w * qv[j].x;
                acc[j].y = acc[j].y * scale + w * qv[j].y;
                acc[j].z = acc[j].z * scale + w * qv[j].z;
                acc[j].w = acc[j].w * scale + w * qv[j].w;
            }
            M = Mn;
        }
    }

    const float invZ = 1.0f / Z;
    float4* O4 = reinterpret_cast<float4*>(out + ((size_t)b * LC + c) * DD);
    #pragma unroll
    for (int j = 0; j < 6; j++)
        O4[lane + 32 * j] = make_float4(cv[j].x * acc[j].x * invZ,
                                        cv[j].y * acc[j].y * invZ,
                                        cv[j].z * acc[j].z * invZ,
                                        cv[j].w * acc[j].w * invZ);
}

// ---------------- host launch ----------------
extern "C" void kernel_launch(void* const* d_in, const int* in_sizes, int n_in,
                              void* d_out, int out_size) {
    const float* a0 = (const float*)d_in[0];
    const float* a1 = (const float*)d_in[1];
    const float* ctx;
    const float* qry;
    if (in_sizes[0] == BB * LC * DD) { ctx = a0; qry = a1; }
    else                             { ctx = a1; qry = a0; }
    float* out = (float*)d_out;

    void *pChi, *pQhi, *pS;
    cudaGetSymbolAddress(&pChi, g_Chi);
    cudaGetSymbolAddress(&pQhi, g_Qhi);
    cudaGetSymbolAddress(&pS, g_S);

    cudaFuncSetAttribute(gemm_hh,
                         cudaFuncAttributeMaxDynamicSharedMemorySize, SM_TOTAL);

    // 1) convert C and Q to bf16 (screening precision)
    {
        int n4 = BB * LC * DD / 4;
        to_bf16_kernel<<<(n4 + 255) / 256, 256>>>(ctx, (bf16*)pChi, n4);
    }
    {
        int n4 = BB * LQ * DD / 4;
        to_bf16_kernel<<<(n4 + 255) / 256, 256>>>(qry, (bf16*)pQhi, n4);
    }
    // 2) screening GEMM: S_approx[c][q] = C . Q^T  (M=LC, N=LQ, K=DD)
    {
        dim3 grid(LQ / 128, LC / 128, BB);   // (4, 16, 8)
        gemm_hh<<<grid, 256, SM_TOTAL>>>(
            (const bf16*)pChi, DD, (long)LC * DD,
            (const bf16*)pQhi, DD, (long)LQ * DD,
            DD / 32,
            (bf16*)pS, LQ, (long)LC * LQ);
    }
    // 3) fused: candidates -> exact logits -> online softmax AWQ -> gate
    {
        dim3 grid(LC / 8, BB);
        softmax_awq_gate<<<grid, 256>>>(qry, ctx, out);
    }
}